// round 10
// baseline (speedup 1.0000x reference)
#include <cuda_runtime.h>
#include <cuda_fp16.h>
#include <math.h>
#include <stdint.h>

#define DIM   256
#define MAXN  100000
#define MAXE  500000

// ---------------- scratch ---------------------------------------------------
__device__ float  g_v[(size_t)MAXN * DIM];
__device__ float  g_comb[(size_t)MAXN * DIM];
__device__ float  g_bq[MAXN];
__device__ float  g_denom[MAXN];
__device__ __half g_bh_v[DIM * DIM];        // Wk^T as fp16, [k][n]
__device__ __half g_bh_g[2 * DIM * DIM];    // Wg   as fp16, [k][n]

// ---------------- helpers ---------------------------------------------------
__device__ __forceinline__ uint32_t smem_u32(const void* p) {
    uint32_t a;
    asm("{ .reg .u64 t; cvta.to.shared.u64 t, %1; cvt.u32.u64 %0, t; }" : "=r"(a) : "l"(p));
    return a;
}
__device__ __forceinline__ void red_add_v4(float* addr, float a, float b, float c, float d) {
    asm volatile("red.global.add.v4.f32 [%0], {%1,%2,%3,%4};"
                 :: "l"(addr), "f"(a), "f"(b), "f"(c), "f"(d) : "memory");
}
__device__ __forceinline__ void cp_async16(uint32_t saddr, const void* gaddr) {
    asm volatile("cp.async.ca.shared.global [%0], [%1], 16;\n" :: "r"(saddr), "l"(gaddr));
}
__device__ __forceinline__ void cp_commit() {
    asm volatile("cp.async.commit_group;\n");
}
__device__ __forceinline__ void ldsm_x4(uint32_t r[4], uint32_t addr) {
    asm volatile("ldmatrix.sync.aligned.m8n8.x4.shared.b16 {%0,%1,%2,%3}, [%4];"
                 : "=r"(r[0]), "=r"(r[1]), "=r"(r[2]), "=r"(r[3]) : "r"(addr));
}
__device__ __forceinline__ void ldsm_x4_t(uint32_t r[4], uint32_t addr) {
    asm volatile("ldmatrix.sync.aligned.m8n8.x4.trans.shared.b16 {%0,%1,%2,%3}, [%4];"
                 : "=r"(r[0]), "=r"(r[1]), "=r"(r[2]), "=r"(r[3]) : "r"(addr));
}
__device__ __forceinline__ void mma_f16(float c[4], const uint32_t a[4], uint32_t b0, uint32_t b1) {
    asm volatile(
        "mma.sync.aligned.m16n8k16.row.col.f32.f16.f16.f32 "
        "{%0,%1,%2,%3}, {%4,%5,%6,%7}, {%8,%9}, {%0,%1,%2,%3};"
        : "+f"(c[0]), "+f"(c[1]), "+f"(c[2]), "+f"(c[3])
        : "r"(a[0]), "r"(a[1]), "r"(a[2]), "r"(a[3]), "r"(b0), "r"(b1));
}

// ---------------- prep: fp16 B images ----------------------------------------
__global__ void k_h_wkT(const float* __restrict__ Wk, __half* __restrict__ dst) {
    __shared__ float t[32][33];
    int bk = blockIdx.x * 32, bn = blockIdx.y * 32;
    int tx = threadIdx.x, ty = threadIdx.y;
    #pragma unroll
    for (int i = 0; i < 32; i += 8)
        t[ty + i][tx] = Wk[(bn + ty + i) * DIM + bk + tx];
    __syncthreads();
    #pragma unroll
    for (int i = 0; i < 32; i += 8)
        dst[(size_t)(bk + ty + i) * DIM + bn + tx] = __float2half(t[tx][ty + i]);
}
__global__ void k_h_wg(const float* __restrict__ Wg, __half* __restrict__ dst) {
    int i = blockIdx.x * blockDim.x + threadIdx.x;
    if (i < 2 * DIM * DIM) dst[i] = __float2half(Wg[i]);
}

// ---------------- fused edge pass: 2 edges per warp, MLP=8 -------------------
__global__ __launch_bounds__(256) void k_edge(const float* __restrict__ x,
                                              const int* __restrict__ idx, int E,
                                              int lo, int hi) {
    int warp = threadIdx.x >> 5, lane = threadIdx.x & 31;
    int e0 = blockIdx.x * 16 + warp * 2;
    int e1 = e0 + 1;
    if (e0 >= E) return;
    int n0 = __ldg(idx + e0);
    int n1 = (e1 < E) ? __ldg(idx + e1) : -1;
    bool d0 = (n0 >= lo) & (n0 < hi);
    bool d1 = (n1 >= lo) & (n1 < hi);
    if (!d0 && !d1) return;

    const float4* xp0 = (const float4*)(x + (size_t)e0 * DIM);
    const float4* xp1 = (const float4*)(x + (size_t)e1 * DIM);
    const float4* vp0 = (const float4*)(g_v + (size_t)(d0 ? n0 : 0) * DIM);
    const float4* vp1 = (const float4*)(g_v + (size_t)(d1 ? n1 : 0) * DIM);

    // front-batch all independent loads (8 in flight when both edges live)
    float4 a0, a1, a2, a3, b0, b1, b2, b3;
    if (d0) { a0 = __ldcs(xp0 + lane); a1 = __ldcs(xp0 + lane + 32);
              b0 = vp0[lane];          b1 = vp0[lane + 32]; }
    if (d1) { a2 = __ldcs(xp1 + lane); a3 = __ldcs(xp1 + lane + 32);
              b2 = vp1[lane];          b3 = vp1[lane + 32]; }

    float s0 = 0.f, s1 = 0.f;
    if (d0) s0 = a0.x * b0.x + a0.y * b0.y + a0.z * b0.z + a0.w * b0.w
               + a1.x * b1.x + a1.y * b1.y + a1.z * b1.z + a1.w * b1.w;
    if (d1) s1 = a2.x * b2.x + a2.y * b2.y + a2.z * b2.z + a2.w * b2.w
               + a3.x * b3.x + a3.y * b3.y + a3.z * b3.z + a3.w * b3.w;
    #pragma unroll
    for (int o = 16; o; o >>= 1) {
        s0 += __shfl_xor_sync(0xffffffffu, s0, o);
        s1 += __shfl_xor_sync(0xffffffffu, s1, o);
    }

    if (d0) {
        float ex = expf((s0 + g_bq[n0]) * 0.0625f);
        if (lane == 0) atomicAdd(&g_denom[n0], ex);
        float* cb = g_comb + (size_t)n0 * DIM;
        red_add_v4(cb + (size_t)lane * 4,        ex * a0.x, ex * a0.y, ex * a0.z, ex * a0.w);
        red_add_v4(cb + (size_t)(lane + 32) * 4, ex * a1.x, ex * a1.y, ex * a1.z, ex * a1.w);
    }
    if (d1) {
        float ex = expf((s1 + g_bq[n1]) * 0.0625f);
        if (lane == 0) atomicAdd(&g_denom[n1], ex);
        float* cb = g_comb + (size_t)n1 * DIM;
        red_add_v4(cb + (size_t)lane * 4,        ex * a2.x, ex * a2.y, ex * a2.z, ex * a2.w);
        red_add_v4(cb + (size_t)(lane + 32) * 4, ex * a3.x, ex * a3.y, ex * a3.z, ex * a3.w);
    }
}

// ---------------- fp16 tensor-core GEMM, BM=64 x BN=256, BK=32 ---------------
#define BM 64
#define BN 256
#define BK 32
#define ASTRH 40
#define BSTRH 264

template<int KT, bool GATE>
__global__ __launch_bounds__(256, 2) void k_gemm_h(const float* __restrict__ Aprev,
                                                   const float* __restrict__ bias,
                                                   float* __restrict__ out, int M) {
    __shared__ __half As[2][BM * ASTRH];
    __shared__ __half Bs[2][BK * BSTRH];
    __shared__ float  bks[DIM];
    __shared__ float  invs[BM];

    const int tid  = threadIdx.x;
    const int lane = tid & 31;
    const int g    = lane >> 2;
    const int tg   = lane & 3;
    const int wid  = tid >> 5;
    const int wR   = (wid & 1) * 32;
    const int wCat = (wid >> 1) * 8;
    const int bm   = blockIdx.x * BM;
    const int lj   = lane >> 3;
    const int lr   = lane & 7;

    if (tid < 64) *(float4*)&bks[tid * 4] = *(const float4*)(bias + tid * 4);
    if (GATE && tid < BM) {
        int r = bm + tid;
        float d = (r < M) ? g_denom[r] : 1.f;
        invs[tid] = 1.f / fmaxf(d, 1e-9f);
    }
    __syncthreads();

    float c[2][8][4];
    #pragma unroll
    for (int mi = 0; mi < 2; mi++)
        #pragma unroll
        for (int ni = 0; ni < 8; ni++)
            #pragma unroll
            for (int q = 0; q < 4; q++) c[mi][ni][q] = 0.f;

    auto ldgA = [&](int it, float4 v[2]) {
        const float* asrc; int k0;
        if (GATE) { if (it < 8) { asrc = (const float*)g_comb; k0 = it * 32; }
                    else        { asrc = Aprev;                k0 = (it - 8) * 32; } }
        else      { asrc = Aprev; k0 = it * 32; }
        #pragma unroll
        for (int j = 0; j < 2; j++) {
            int seg = tid + j * 256;
            int row = seg >> 3, c4 = (seg & 7) * 4;
            int gr = bm + row; if (gr >= M) gr = M - 1;
            v[j] = *(const float4*)(asrc + (size_t)gr * DIM + k0 + c4);
        }
    };
    auto stsA = [&](int it, int buf, const float4 v[2]) {
        bool sc = GATE && (it < 8);
        #pragma unroll
        for (int j = 0; j < 2; j++) {
            int seg = tid + j * 256;
            int row = seg >> 3, c4 = (seg & 7) * 4;
            float4 w = v[j];
            if (sc) { float iv = invs[row]; w.x *= iv; w.y *= iv; w.z *= iv; w.w *= iv; }
            __half2 h0 = __floats2half2_rn(w.x, w.y);
            __half2 h1 = __floats2half2_rn(w.z, w.w);
            uint2 pk = make_uint2(*(uint32_t*)&h0, *(uint32_t*)&h1);
            *(uint2*)&As[buf][row * ASTRH + c4] = pk;
        }
    };
    auto stageB = [&](int it, int buf) {
        const __half* bh = GATE ? (const __half*)g_bh_g : (const __half*)g_bh_v;
        int kb = GATE ? (it < 8 ? 256 + it * 32 : (it - 8) * 32) : it * 32;
        #pragma unroll
        for (int j = 0; j < 4; j++) {
            int seg = tid + j * 256;
            int kr = seg >> 5, c8 = (seg & 31) * 8;
            cp_async16(smem_u32(&Bs[buf][kr * BSTRH + c8]),
                       bh + (size_t)(kb + kr) * DIM + c8);
        }
        cp_commit();
    };

    float4 vA[2], vN[2];
    ldgA(0, vA); stsA(0, 0, vA); stageB(0, 0);

    float bqacc = 0.f;
    const int bq_row = tid >> 2;
    const int bq_q   = tid & 3;

    #pragma unroll 1
    for (int it = 0; it < KT; it++) {
        int buf = it & 1;
        if (it + 1 < KT) {
            ldgA(it + 1, vN);
            stageB(it + 1, (it + 1) & 1);
            asm volatile("cp.async.wait_group 1;\n" ::: "memory");
        } else {
            asm volatile("cp.async.wait_group 0;\n" ::: "memory");
        }
        __syncthreads();

        const __half* Ab = As[buf];
        const __half* Bb = Bs[buf];
        #pragma unroll
        for (int ks = 0; ks < BK; ks += 16) {
            uint32_t a[2][4];
            #pragma unroll
            for (int mi = 0; mi < 2; mi++) {
                uint32_t ad = smem_u32(&Ab[(wR + mi * 16 + (lj & 1) * 8 + lr) * ASTRH
                                           + ks + (lj >> 1) * 8]);
                ldsm_x4(a[mi], ad);
            }
            #pragma unroll
            for (int nn = 0; nn < 4; nn++) {
                uint32_t b[4];
                uint32_t bd = smem_u32(&Bb[(ks + (lj & 1) * 8 + lr) * BSTRH
                                           + (wCat + nn * 2 + (lj >> 1)) * 8]);
                ldsm_x4_t(b, bd);
                #pragma unroll
                for (int mi = 0; mi < 2; mi++) {
                    mma_f16(c[mi][nn * 2 + 0], a[mi], b[0], b[1]);
                    mma_f16(c[mi][nn * 2 + 1], a[mi], b[2], b[3]);
                }
            }
        }

        if (!GATE) {
            float s = 0.f;
            #pragma unroll
            for (int j = 0; j < 8; j++)
                s += __half2float(Ab[bq_row * ASTRH + bq_q * 8 + j])
                   * bks[it * 32 + bq_q * 8 + j];
            bqacc += s;
        }

        if (it + 1 < KT) stsA(it + 1, (it + 1) & 1, vN);
        __syncthreads();
    }

    if (!GATE) {
        bqacc += __shfl_xor_sync(0xffffffffu, bqacc, 1);
        bqacc += __shfl_xor_sync(0xffffffffu, bqacc, 2);
        if (bq_q == 0 && bm + bq_row < M) g_bq[bm + bq_row] = bqacc;
        if (tid < BM && bm + tid < M) g_denom[bm + tid] = 0.f;
    }

    #pragma unroll
    for (int mi = 0; mi < 2; mi++) {
        #pragma unroll
        for (int half = 0; half < 2; half++) {
            int lrow = wR + mi * 16 + g + half * 8;
            int r = bm + lrow;
            if (r >= M) continue;
            #pragma unroll
            for (int ni = 0; ni < 8; ni++) {
                int cc = wCat * 8 + ni * 8 + tg * 2;
                float v0 = c[mi][ni][half * 2 + 0];
                float v1 = c[mi][ni][half * 2 + 1];
                if (GATE) {
                    float2 pv = *(const float2*)(Aprev + (size_t)r * DIM + cc);
                    float2 cv = *(const float2*)(g_comb + (size_t)r * DIM + cc);
                    float iv = invs[lrow];
                    float g0 = 1.f / (1.f + expf(-(v0 + bks[cc])));
                    float g1 = 1.f / (1.f + expf(-(v1 + bks[cc + 1])));
                    float2 o;
                    o.x = g0 * pv.x + (1.f - g0) * (cv.x * iv);
                    o.y = g1 * pv.y + (1.f - g1) * (cv.y * iv);
                    *(float2*)(out + (size_t)r * DIM + cc) = o;
                } else {
                    *(float2*)(g_v + (size_t)r * DIM + cc) = make_float2(v0, v1);
                    *(float2*)(g_comb + (size_t)r * DIM + cc) = make_float2(0.f, 0.f);
                }
            }
        }
    }
}

// ---------------- launch ------------------------------------------------------
extern "C" void kernel_launch(void* const* d_in, const int* in_sizes, int n_in,
                              void* d_out, int out_size) {
    const float* x    = (const float*)d_in[0];
    const float* prev = (const float*)d_in[1];
    const float* Wk   = (const float*)d_in[2];
    const float* bk   = (const float*)d_in[3];
    const float* Wg   = (const float*)d_in[4];
    const float* bg   = (const float*)d_in[5];
    const int*   idx  = (const int*)d_in[6];
    float* out = (float*)d_out;

    int Dv = in_sizes[3];            // 256
    int E  = in_sizes[0] / Dv;
    int N  = in_sizes[1] / Dv;

    __half* bhv = nullptr; cudaGetSymbolAddress((void**)&bhv, g_bh_v);
    __half* bhg = nullptr; cudaGetSymbolAddress((void**)&bhg, g_bh_g);
    k_h_wkT<<<dim3(8, 8), dim3(32, 8)>>>(Wk, bhv);
    k_h_wg<<<(2 * DIM * DIM + 255) / 256, 256>>>(Wg, bhg);

    int gb = (N + BM - 1) / BM;
    k_gemm_h<8, false><<<gb, 256>>>(prev, bk, nullptr, N);

    int Nh = N / 2;
    int eg = (E + 15) / 16;
    k_edge<<<eg, 256>>>(x, idx, E, 0, Nh);
    k_edge<<<eg, 256>>>(x, idx, E, Nh, N);

    k_gemm_h<16, true><<<gb, 256>>>(prev, bg, out, N);
}

// round 11
// speedup vs baseline: 1.0166x; 1.0166x over previous
#include <cuda_runtime.h>
#include <cuda_fp16.h>
#include <math.h>
#include <stdint.h>

#define DIM   256
#define MAXN  100000
#define MAXE  500000

// ---------------- scratch ---------------------------------------------------
__device__ __half g_vh[(size_t)MAXN * DIM];   // v in fp16 (halves gather traffic)
__device__ float  g_comb[(size_t)MAXN * DIM];
__device__ float  g_bq[MAXN];
__device__ float  g_denom[MAXN];
__device__ __half g_bh_v[DIM * DIM];          // Wk^T as fp16, [k][n]
__device__ __half g_bh_g[2 * DIM * DIM];      // Wg   as fp16, [k][n]

// ---------------- helpers ---------------------------------------------------
__device__ __forceinline__ uint32_t smem_u32(const void* p) {
    uint32_t a;
    asm("{ .reg .u64 t; cvta.to.shared.u64 t, %1; cvt.u32.u64 %0, t; }" : "=r"(a) : "l"(p));
    return a;
}
__device__ __forceinline__ void red_add_v4(float* addr, float a, float b, float c, float d) {
    asm volatile("red.global.add.v4.f32 [%0], {%1,%2,%3,%4};"
                 :: "l"(addr), "f"(a), "f"(b), "f"(c), "f"(d) : "memory");
}
__device__ __forceinline__ void cp_async16(uint32_t saddr, const void* gaddr) {
    asm volatile("cp.async.ca.shared.global [%0], [%1], 16;\n" :: "r"(saddr), "l"(gaddr));
}
__device__ __forceinline__ void cp_commit() {
    asm volatile("cp.async.commit_group;\n");
}
__device__ __forceinline__ void ldsm_x4(uint32_t r[4], uint32_t addr) {
    asm volatile("ldmatrix.sync.aligned.m8n8.x4.shared.b16 {%0,%1,%2,%3}, [%4];"
                 : "=r"(r[0]), "=r"(r[1]), "=r"(r[2]), "=r"(r[3]) : "r"(addr));
}
__device__ __forceinline__ void ldsm_x4_t(uint32_t r[4], uint32_t addr) {
    asm volatile("ldmatrix.sync.aligned.m8n8.x4.trans.shared.b16 {%0,%1,%2,%3}, [%4];"
                 : "=r"(r[0]), "=r"(r[1]), "=r"(r[2]), "=r"(r[3]) : "r"(addr));
}
__device__ __forceinline__ void mma_f16(float c[4], const uint32_t a[4], uint32_t b0, uint32_t b1) {
    asm volatile(
        "mma.sync.aligned.m16n8k16.row.col.f32.f16.f16.f32 "
        "{%0,%1,%2,%3}, {%4,%5,%6,%7}, {%8,%9}, {%0,%1,%2,%3};"
        : "+f"(c[0]), "+f"(c[1]), "+f"(c[2]), "+f"(c[3])
        : "r"(a[0]), "r"(a[1]), "r"(a[2]), "r"(a[3]), "r"(b0), "r"(b1));
}

// ---------------- prep: fp16 B images ----------------------------------------
__global__ void k_h_wkT(const float* __restrict__ Wk, __half* __restrict__ dst) {
    __shared__ float t[32][33];
    int bk = blockIdx.x * 32, bn = blockIdx.y * 32;
    int tx = threadIdx.x, ty = threadIdx.y;
    #pragma unroll
    for (int i = 0; i < 32; i += 8)
        t[ty + i][tx] = Wk[(bn + ty + i) * DIM + bk + tx];
    __syncthreads();
    #pragma unroll
    for (int i = 0; i < 32; i += 8)
        dst[(size_t)(bk + ty + i) * DIM + bn + tx] = __float2half(t[tx][ty + i]);
}
__global__ void k_h_wg(const float* __restrict__ Wg, __half* __restrict__ dst) {
    int i = blockIdx.x * blockDim.x + threadIdx.x;
    if (i < 2 * DIM * DIM) dst[i] = __float2half(Wg[i]);
}

// ---------------- fused edge pass (1 edge/warp; fp16 v gather) ---------------
// Lane owns cols [8*lane, 8*lane+8): x via 2 float4, v via 1 uint4 (8 halves).
__global__ __launch_bounds__(256) void k_edge(const float* __restrict__ x,
                                              const int* __restrict__ idx, int E,
                                              int lo, int hi) {
    int warp = threadIdx.x >> 5, lane = threadIdx.x & 31;
    int e = blockIdx.x * 8 + warp;
    if (e >= E) return;
    int n = __ldg(idx + e);
    if (n < lo || n >= hi) return;

    const float4* xp = (const float4*)(x + (size_t)e * DIM);
    const uint4*  vp = (const uint4*)(g_vh + (size_t)n * DIM);
    float4 a0 = __ldcs(xp + 2 * lane);
    float4 a1 = __ldcs(xp + 2 * lane + 1);
    uint4  hv = vp[lane];

    float2 f0 = __half22float2(*(__half2*)&hv.x);
    float2 f1 = __half22float2(*(__half2*)&hv.y);
    float2 f2 = __half22float2(*(__half2*)&hv.z);
    float2 f3 = __half22float2(*(__half2*)&hv.w);
    float s = a0.x * f0.x + a0.y * f0.y + a0.z * f1.x + a0.w * f1.y
            + a1.x * f2.x + a1.y * f2.y + a1.z * f3.x + a1.w * f3.y;
    #pragma unroll
    for (int o = 16; o; o >>= 1) s += __shfl_xor_sync(0xffffffffu, s, o);

    float ex = expf((s + g_bq[n]) * 0.0625f);
    if (lane == 0) atomicAdd(&g_denom[n], ex);
    float* cb = g_comb + (size_t)n * DIM + (size_t)lane * 8;
    red_add_v4(cb,     ex * a0.x, ex * a0.y, ex * a0.z, ex * a0.w);
    red_add_v4(cb + 4, ex * a1.x, ex * a1.y, ex * a1.z, ex * a1.w);
}

// ---------------- fp16 tensor-core GEMM, BM=64 x BN=256, BK=32 ---------------
#define BM 64
#define BN 256
#define BK 32
#define ASTRH 40
#define BSTRH 264

template<int KT, bool GATE>
__global__ __launch_bounds__(256, 2) void k_gemm_h(const float* __restrict__ Aprev,
                                                   const float* __restrict__ bias,
                                                   float* __restrict__ out, int M) {
    __shared__ __half As[2][BM * ASTRH];
    __shared__ __half Bs[2][BK * BSTRH];
    __shared__ float  bks[DIM];
    __shared__ float  invs[BM];

    const int tid  = threadIdx.x;
    const int lane = tid & 31;
    const int g    = lane >> 2;
    const int tg   = lane & 3;
    const int wid  = tid >> 5;
    const int wR   = (wid & 1) * 32;
    const int wCat = (wid >> 1) * 8;
    const int bm   = blockIdx.x * BM;
    const int lj   = lane >> 3;
    const int lr   = lane & 7;

    if (tid < 64) *(float4*)&bks[tid * 4] = *(const float4*)(bias + tid * 4);
    if (GATE && tid < BM) {
        int r = bm + tid;
        float d = (r < M) ? g_denom[r] : 1.f;
        invs[tid] = 1.f / fmaxf(d, 1e-9f);
    }
    __syncthreads();

    float c[2][8][4];
    #pragma unroll
    for (int mi = 0; mi < 2; mi++)
        #pragma unroll
        for (int ni = 0; ni < 8; ni++)
            #pragma unroll
            for (int q = 0; q < 4; q++) c[mi][ni][q] = 0.f;

    auto ldgA = [&](int it, float4 v[2]) {
        const float* asrc; int k0;
        if (GATE) { if (it < 8) { asrc = (const float*)g_comb; k0 = it * 32; }
                    else        { asrc = Aprev;                k0 = (it - 8) * 32; } }
        else      { asrc = Aprev; k0 = it * 32; }
        #pragma unroll
        for (int j = 0; j < 2; j++) {
            int seg = tid + j * 256;
            int row = seg >> 3, c4 = (seg & 7) * 4;
            int gr = bm + row; if (gr >= M) gr = M - 1;
            v[j] = *(const float4*)(asrc + (size_t)gr * DIM + k0 + c4);
        }
    };
    auto stsA = [&](int it, int buf, const float4 v[2]) {
        bool sc = GATE && (it < 8);
        #pragma unroll
        for (int j = 0; j < 2; j++) {
            int seg = tid + j * 256;
            int row = seg >> 3, c4 = (seg & 7) * 4;
            float4 w = v[j];
            if (sc) { float iv = invs[row]; w.x *= iv; w.y *= iv; w.z *= iv; w.w *= iv; }
            __half2 h0 = __floats2half2_rn(w.x, w.y);
            __half2 h1 = __floats2half2_rn(w.z, w.w);
            uint2 pk = make_uint2(*(uint32_t*)&h0, *(uint32_t*)&h1);
            *(uint2*)&As[buf][row * ASTRH + c4] = pk;
        }
    };
    auto stageB = [&](int it, int buf) {
        const __half* bh = GATE ? (const __half*)g_bh_g : (const __half*)g_bh_v;
        int kb = GATE ? (it < 8 ? 256 + it * 32 : (it - 8) * 32) : it * 32;
        #pragma unroll
        for (int j = 0; j < 4; j++) {
            int seg = tid + j * 256;
            int kr = seg >> 5, c8 = (seg & 31) * 8;
            cp_async16(smem_u32(&Bs[buf][kr * BSTRH + c8]),
                       bh + (size_t)(kb + kr) * DIM + c8);
        }
        cp_commit();
    };

    float4 vA[2], vN[2];
    ldgA(0, vA); stsA(0, 0, vA); stageB(0, 0);

    float bqacc = 0.f;
    const int bq_row = tid >> 2;
    const int bq_q   = tid & 3;

    #pragma unroll 1
    for (int it = 0; it < KT; it++) {
        int buf = it & 1;
        if (it + 1 < KT) {
            ldgA(it + 1, vN);
            stageB(it + 1, (it + 1) & 1);
            asm volatile("cp.async.wait_group 1;\n" ::: "memory");
        } else {
            asm volatile("cp.async.wait_group 0;\n" ::: "memory");
        }
        __syncthreads();

        const __half* Ab = As[buf];
        const __half* Bb = Bs[buf];
        #pragma unroll
        for (int ks = 0; ks < BK; ks += 16) {
            uint32_t a[2][4];
            #pragma unroll
            for (int mi = 0; mi < 2; mi++) {
                uint32_t ad = smem_u32(&Ab[(wR + mi * 16 + (lj & 1) * 8 + lr) * ASTRH
                                           + ks + (lj >> 1) * 8]);
                ldsm_x4(a[mi], ad);
            }
            #pragma unroll
            for (int nn = 0; nn < 4; nn++) {
                uint32_t b[4];
                uint32_t bd = smem_u32(&Bb[(ks + (lj & 1) * 8 + lr) * BSTRH
                                           + (wCat + nn * 2 + (lj >> 1)) * 8]);
                ldsm_x4_t(b, bd);
                #pragma unroll
                for (int mi = 0; mi < 2; mi++) {
                    mma_f16(c[mi][nn * 2 + 0], a[mi], b[0], b[1]);
                    mma_f16(c[mi][nn * 2 + 1], a[mi], b[2], b[3]);
                }
            }
        }

        if (!GATE) {
            float s = 0.f;
            #pragma unroll
            for (int j = 0; j < 8; j++)
                s += __half2float(Ab[bq_row * ASTRH + bq_q * 8 + j])
                   * bks[it * 32 + bq_q * 8 + j];
            bqacc += s;
        }

        if (it + 1 < KT) stsA(it + 1, (it + 1) & 1, vN);
        __syncthreads();
    }

    if (!GATE) {
        bqacc += __shfl_xor_sync(0xffffffffu, bqacc, 1);
        bqacc += __shfl_xor_sync(0xffffffffu, bqacc, 2);
        if (bq_q == 0 && bm + bq_row < M) g_bq[bm + bq_row] = bqacc;
        if (tid < BM && bm + tid < M) g_denom[bm + tid] = 0.f;
    }

    #pragma unroll
    for (int mi = 0; mi < 2; mi++) {
        #pragma unroll
        for (int half = 0; half < 2; half++) {
            int lrow = wR + mi * 16 + g + half * 8;
            int r = bm + lrow;
            if (r >= M) continue;
            #pragma unroll
            for (int ni = 0; ni < 8; ni++) {
                int cc = wCat * 8 + ni * 8 + tg * 2;
                float v0 = c[mi][ni][half * 2 + 0];
                float v1 = c[mi][ni][half * 2 + 1];
                if (GATE) {
                    float2 pv = *(const float2*)(Aprev + (size_t)r * DIM + cc);
                    float2 cv = *(const float2*)(g_comb + (size_t)r * DIM + cc);
                    float iv = invs[lrow];
                    float g0 = 1.f / (1.f + expf(-(v0 + bks[cc])));
                    float g1 = 1.f / (1.f + expf(-(v1 + bks[cc + 1])));
                    float2 o;
                    o.x = g0 * pv.x + (1.f - g0) * (cv.x * iv);
                    o.y = g1 * pv.y + (1.f - g1) * (cv.y * iv);
                    *(float2*)(out + (size_t)r * DIM + cc) = o;
                } else {
                    __half2 hv = __floats2half2_rn(v0, v1);
                    *(uint32_t*)(g_vh + (size_t)r * DIM + cc) = *(uint32_t*)&hv;
                    *(float2*)(g_comb + (size_t)r * DIM + cc) = make_float2(0.f, 0.f);
                }
            }
        }
    }
}

// ---------------- launch ------------------------------------------------------
extern "C" void kernel_launch(void* const* d_in, const int* in_sizes, int n_in,
                              void* d_out, int out_size) {
    const float* x    = (const float*)d_in[0];
    const float* prev = (const float*)d_in[1];
    const float* Wk   = (const float*)d_in[2];
    const float* bk   = (const float*)d_in[3];
    const float* Wg   = (const float*)d_in[4];
    const float* bg   = (const float*)d_in[5];
    const int*   idx  = (const int*)d_in[6];
    float* out = (float*)d_out;

    int Dv = in_sizes[3];            // 256
    int E  = in_sizes[0] / Dv;
    int N  = in_sizes[1] / Dv;

    __half* bhv = nullptr; cudaGetSymbolAddress((void**)&bhv, g_bh_v);
    __half* bhg = nullptr; cudaGetSymbolAddress((void**)&bhg, g_bh_g);
    k_h_wkT<<<dim3(8, 8), dim3(32, 8)>>>(Wk, bhv);
    k_h_wg<<<(2 * DIM * DIM + 255) / 256, 256>>>(Wg, bhg);

    int gb = (N + BM - 1) / BM;
    k_gemm_h<8, false><<<gb, 256>>>(prev, bk, nullptr, N);

    int Nh = N / 2;
    int eg = (E + 7) / 8;
    k_edge<<<eg, 256>>>(x, idx, E, 0, Nh);
    k_edge<<<eg, 256>>>(x, idx, E, Nh, N);

    k_gemm_h<16, true><<<gb, 256>>>(prev, bg, out, N);
}

// round 12
// speedup vs baseline: 1.0798x; 1.0622x over previous
#include <cuda_runtime.h>
#include <cuda_fp16.h>
#include <math.h>
#include <stdint.h>

#define DIM   256
#define MAXN  100000
#define MAXE  500000

// ---------------- scratch ---------------------------------------------------
__device__ __half g_vh[(size_t)MAXN * DIM];   // v in fp16
__device__ float  g_comb[(size_t)MAXN * DIM];
__device__ float  g_bq[MAXN];
__device__ float  g_denom[MAXN];
__device__ __half g_bh_v[DIM * DIM];          // Wk^T as fp16, [k][n]
__device__ __half g_bh_g[2 * DIM * DIM];      // Wg   as fp16, [k][n]

// ---------------- helpers ---------------------------------------------------
__device__ __forceinline__ uint32_t smem_u32(const void* p) {
    uint32_t a;
    asm("{ .reg .u64 t; cvta.to.shared.u64 t, %1; cvt.u32.u64 %0, t; }" : "=r"(a) : "l"(p));
    return a;
}
__device__ __forceinline__ void red_add_v4(float* addr, float a, float b, float c, float d) {
    asm volatile("red.global.add.v4.f32 [%0], {%1,%2,%3,%4};"
                 :: "l"(addr), "f"(a), "f"(b), "f"(c), "f"(d) : "memory");
}
__device__ __forceinline__ void cp_async16(uint32_t saddr, const void* gaddr) {
    asm volatile("cp.async.ca.shared.global [%0], [%1], 16;\n" :: "r"(saddr), "l"(gaddr));
}
__device__ __forceinline__ void cp_commit() {
    asm volatile("cp.async.commit_group;\n");
}
__device__ __forceinline__ void ldsm_x4(uint32_t r[4], uint32_t addr) {
    asm volatile("ldmatrix.sync.aligned.m8n8.x4.shared.b16 {%0,%1,%2,%3}, [%4];"
                 : "=r"(r[0]), "=r"(r[1]), "=r"(r[2]), "=r"(r[3]) : "r"(addr));
}
__device__ __forceinline__ void ldsm_x4_t(uint32_t r[4], uint32_t addr) {
    asm volatile("ldmatrix.sync.aligned.m8n8.x4.trans.shared.b16 {%0,%1,%2,%3}, [%4];"
                 : "=r"(r[0]), "=r"(r[1]), "=r"(r[2]), "=r"(r[3]) : "r"(addr));
}
__device__ __forceinline__ void mma_f16(float c[4], const uint32_t a[4], uint32_t b0, uint32_t b1) {
    asm volatile(
        "mma.sync.aligned.m16n8k16.row.col.f32.f16.f16.f32 "
        "{%0,%1,%2,%3}, {%4,%5,%6,%7}, {%8,%9}, {%0,%1,%2,%3};"
        : "+f"(c[0]), "+f"(c[1]), "+f"(c[2]), "+f"(c[3])
        : "r"(a[0]), "r"(a[1]), "r"(a[2]), "r"(a[3]), "r"(b0), "r"(b1));
}

// ---------------- prep: fp16 B images ----------------------------------------
__global__ void k_h_wkT(const float* __restrict__ Wk, __half* __restrict__ dst) {
    __shared__ float t[32][33];
    int bk = blockIdx.x * 32, bn = blockIdx.y * 32;
    int tx = threadIdx.x, ty = threadIdx.y;
    #pragma unroll
    for (int i = 0; i < 32; i += 8)
        t[ty + i][tx] = Wk[(bn + ty + i) * DIM + bk + tx];
    __syncthreads();
    #pragma unroll
    for (int i = 0; i < 32; i += 8)
        dst[(size_t)(bk + ty + i) * DIM + bn + tx] = __float2half(t[tx][ty + i]);
}
__global__ void k_h_wg(const float* __restrict__ Wg, __half* __restrict__ dst) {
    int i = blockIdx.x * blockDim.x + threadIdx.x;
    if (i < 2 * DIM * DIM) dst[i] = __float2half(Wg[i]);
}

// ---------------- fused edge pass: round-9 dense layout, fp16 v --------------
// Lane covers cols [4*lane,4*lane+4) and [128+4*lane,128+4*lane+4).
// x: 2x float4 (dense 512B/warp-load); v: 2x uint2 fp16 (dense 256B/warp-load).
__global__ __launch_bounds__(256) void k_edge(const float* __restrict__ x,
                                              const int* __restrict__ idx, int E,
                                              int lo, int hi) {
    int warp = threadIdx.x >> 5, lane = threadIdx.x & 31;
    int e = blockIdx.x * 8 + warp;
    if (e >= E) return;
    int n = __ldg(idx + e);
    if (n < lo || n >= hi) return;

    const float4* xp = (const float4*)(x + (size_t)e * DIM);
    const uint2*  vp = (const uint2*)(g_vh + (size_t)n * DIM);
    float4 a0 = __ldcs(xp + lane);
    float4 a1 = __ldcs(xp + lane + 32);
    uint2  h0 = vp[lane];
    uint2  h1 = vp[lane + 32];

    float2 v0 = __half22float2(*(__half2*)&h0.x);
    float2 v1 = __half22float2(*(__half2*)&h0.y);
    float2 v2 = __half22float2(*(__half2*)&h1.x);
    float2 v3 = __half22float2(*(__half2*)&h1.y);
    float s = a0.x * v0.x + a0.y * v0.y + a0.z * v1.x + a0.w * v1.y
            + a1.x * v2.x + a1.y * v2.y + a1.z * v3.x + a1.w * v3.y;
    #pragma unroll
    for (int o = 16; o; o >>= 1) s += __shfl_xor_sync(0xffffffffu, s, o);

    float ex = expf((s + g_bq[n]) * 0.0625f);
    if (lane == 0) atomicAdd(&g_denom[n], ex);
    float* cb = g_comb + (size_t)n * DIM;
    red_add_v4(cb + (size_t)lane * 4,        ex * a0.x, ex * a0.y, ex * a0.z, ex * a0.w);
    red_add_v4(cb + (size_t)(lane + 32) * 4, ex * a1.x, ex * a1.y, ex * a1.z, ex * a1.w);
}

// ---------------- fp16 tensor-core GEMM, BM=64 x BN=256, BK=32 ---------------
#define BM 64
#define BN 256
#define BK 32
#define ASTRH 40
#define BSTRH 264

template<int KT, bool GATE>
__global__ __launch_bounds__(256, 2) void k_gemm_h(const float* __restrict__ Aprev,
                                                   const float* __restrict__ bias,
                                                   float* __restrict__ out, int M) {
    __shared__ __half As[2][BM * ASTRH];
    __shared__ __half Bs[2][BK * BSTRH];
    __shared__ float  bks[DIM];
    __shared__ float  invs[BM];

    const int tid  = threadIdx.x;
    const int lane = tid & 31;
    const int g    = lane >> 2;
    const int tg   = lane & 3;
    const int wid  = tid >> 5;
    const int wR   = (wid & 1) * 32;
    const int wCat = (wid >> 1) * 8;
    const int bm   = blockIdx.x * BM;
    const int lj   = lane >> 3;
    const int lr   = lane & 7;

    if (tid < 64) *(float4*)&bks[tid * 4] = *(const float4*)(bias + tid * 4);
    if (GATE && tid < BM) {
        int r = bm + tid;
        float d = (r < M) ? g_denom[r] : 1.f;
        invs[tid] = 1.f / fmaxf(d, 1e-9f);
    }
    __syncthreads();

    float c[2][8][4];
    #pragma unroll
    for (int mi = 0; mi < 2; mi++)
        #pragma unroll
        for (int ni = 0; ni < 8; ni++)
            #pragma unroll
            for (int q = 0; q < 4; q++) c[mi][ni][q] = 0.f;

    auto ldgA = [&](int it, float4 v[2]) {
        const float* asrc; int k0;
        if (GATE) { if (it < 8) { asrc = (const float*)g_comb; k0 = it * 32; }
                    else        { asrc = Aprev;                k0 = (it - 8) * 32; } }
        else      { asrc = Aprev; k0 = it * 32; }
        #pragma unroll
        for (int j = 0; j < 2; j++) {
            int seg = tid + j * 256;
            int row = seg >> 3, c4 = (seg & 7) * 4;
            int gr = bm + row; if (gr >= M) gr = M - 1;
            v[j] = *(const float4*)(asrc + (size_t)gr * DIM + k0 + c4);
        }
    };
    auto stsA = [&](int it, int buf, const float4 v[2]) {
        bool sc = GATE && (it < 8);
        #pragma unroll
        for (int j = 0; j < 2; j++) {
            int seg = tid + j * 256;
            int row = seg >> 3, c4 = (seg & 7) * 4;
            float4 w = v[j];
            if (sc) { float iv = invs[row]; w.x *= iv; w.y *= iv; w.z *= iv; w.w *= iv; }
            __half2 h0 = __floats2half2_rn(w.x, w.y);
            __half2 h1 = __floats2half2_rn(w.z, w.w);
            uint2 pk = make_uint2(*(uint32_t*)&h0, *(uint32_t*)&h1);
            *(uint2*)&As[buf][row * ASTRH + c4] = pk;
        }
    };
    auto stageB = [&](int it, int buf) {
        const __half* bh = GATE ? (const __half*)g_bh_g : (const __half*)g_bh_v;
        int kb = GATE ? (it < 8 ? 256 + it * 32 : (it - 8) * 32) : it * 32;
        #pragma unroll
        for (int j = 0; j < 4; j++) {
            int seg = tid + j * 256;
            int kr = seg >> 5, c8 = (seg & 31) * 8;
            cp_async16(smem_u32(&Bs[buf][kr * BSTRH + c8]),
                       bh + (size_t)(kb + kr) * DIM + c8);
        }
        cp_commit();
    };

    float4 vA[2], vN[2];
    ldgA(0, vA); stsA(0, 0, vA); stageB(0, 0);

    float bqacc = 0.f;
    const int bq_row = tid >> 2;
    const int bq_q   = tid & 3;

    #pragma unroll 1
    for (int it = 0; it < KT; it++) {
        int buf = it & 1;
        if (it + 1 < KT) {
            ldgA(it + 1, vN);
            stageB(it + 1, (it + 1) & 1);
            asm volatile("cp.async.wait_group 1;\n" ::: "memory");
        } else {
            asm volatile("cp.async.wait_group 0;\n" ::: "memory");
        }
        __syncthreads();

        const __half* Ab = As[buf];
        const __half* Bb = Bs[buf];
        #pragma unroll
        for (int ks = 0; ks < BK; ks += 16) {
            uint32_t a[2][4];
            #pragma unroll
            for (int mi = 0; mi < 2; mi++) {
                uint32_t ad = smem_u32(&Ab[(wR + mi * 16 + (lj & 1) * 8 + lr) * ASTRH
                                           + ks + (lj >> 1) * 8]);
                ldsm_x4(a[mi], ad);
            }
            #pragma unroll
            for (int nn = 0; nn < 4; nn++) {
                uint32_t b[4];
                uint32_t bd = smem_u32(&Bb[(ks + (lj & 1) * 8 + lr) * BSTRH
                                           + (wCat + nn * 2 + (lj >> 1)) * 8]);
                ldsm_x4_t(b, bd);
                #pragma unroll
                for (int mi = 0; mi < 2; mi++) {
                    mma_f16(c[mi][nn * 2 + 0], a[mi], b[0], b[1]);
                    mma_f16(c[mi][nn * 2 + 1], a[mi], b[2], b[3]);
                }
            }
        }

        if (!GATE) {
            float s = 0.f;
            #pragma unroll
            for (int j = 0; j < 8; j++)
                s += __half2float(Ab[bq_row * ASTRH + bq_q * 8 + j])
                   * bks[it * 32 + bq_q * 8 + j];
            bqacc += s;
        }

        if (it + 1 < KT) stsA(it + 1, (it + 1) & 1, vN);
        __syncthreads();
    }

    if (!GATE) {
        bqacc += __shfl_xor_sync(0xffffffffu, bqacc, 1);
        bqacc += __shfl_xor_sync(0xffffffffu, bqacc, 2);
        if (bq_q == 0 && bm + bq_row < M) g_bq[bm + bq_row] = bqacc;
        if (tid < BM && bm + tid < M) g_denom[bm + tid] = 0.f;
    }

    #pragma unroll
    for (int mi = 0; mi < 2; mi++) {
        #pragma unroll
        for (int half = 0; half < 2; half++) {
            int lrow = wR + mi * 16 + g + half * 8;
            int r = bm + lrow;
            if (r >= M) continue;
            #pragma unroll
            for (int ni = 0; ni < 8; ni++) {
                int cc = wCat * 8 + ni * 8 + tg * 2;
                float v0 = c[mi][ni][half * 2 + 0];
                float v1 = c[mi][ni][half * 2 + 1];
                if (GATE) {
                    float2 pv = *(const float2*)(Aprev + (size_t)r * DIM + cc);
                    float2 cv = *(const float2*)(g_comb + (size_t)r * DIM + cc);
                    float iv = invs[lrow];
                    float g0 = 1.f / (1.f + expf(-(v0 + bks[cc])));
                    float g1 = 1.f / (1.f + expf(-(v1 + bks[cc + 1])));
                    float2 o;
                    o.x = g0 * pv.x + (1.f - g0) * (cv.x * iv);
                    o.y = g1 * pv.y + (1.f - g1) * (cv.y * iv);
                    *(float2*)(out + (size_t)r * DIM + cc) = o;
                } else {
                    __half2 hv = __floats2half2_rn(v0, v1);
                    *(uint32_t*)(g_vh + (size_t)r * DIM + cc) = *(uint32_t*)&hv;
                    *(float2*)(g_comb + (size_t)r * DIM + cc) = make_float2(0.f, 0.f);
                }
            }
        }
    }
}

// ---------------- launch ------------------------------------------------------
extern "C" void kernel_launch(void* const* d_in, const int* in_sizes, int n_in,
                              void* d_out, int out_size) {
    const float* x    = (const float*)d_in[0];
    const float* prev = (const float*)d_in[1];
    const float* Wk   = (const float*)d_in[2];
    const float* bk   = (const float*)d_in[3];
    const float* Wg   = (const float*)d_in[4];
    const float* bg   = (const float*)d_in[5];
    const int*   idx  = (const int*)d_in[6];
    float* out = (float*)d_out;

    int Dv = in_sizes[3];            // 256
    int E  = in_sizes[0] / Dv;
    int N  = in_sizes[1] / Dv;

    __half* bhv = nullptr; cudaGetSymbolAddress((void**)&bhv, g_bh_v);
    __half* bhg = nullptr; cudaGetSymbolAddress((void**)&bhg, g_bh_g);
    k_h_wkT<<<dim3(8, 8), dim3(32, 8)>>>(Wk, bhv);
    k_h_wg<<<(2 * DIM * DIM + 255) / 256, 256>>>(Wg, bhg);

    int gb = (N + BM - 1) / BM;
    k_gemm_h<8, false><<<gb, 256>>>(prev, bk, nullptr, N);

    int Nh = N / 2;
    int eg = (E + 7) / 8;
    k_edge<<<eg, 256>>>(x, idx, E, 0, Nh);
    k_edge<<<eg, 256>>>(x, idx, E, Nh, N);

    k_gemm_h<16, true><<<gb, 256>>>(prev, bg, out, N);
}

// round 13
// speedup vs baseline: 1.1914x; 1.1033x over previous
#include <cuda_runtime.h>
#include <cuda_fp16.h>
#include <math.h>
#include <stdint.h>

#define DIM   256
#define MAXN  100000
#define MAXE  500000
#define BCAP  64

// ---------------- scratch ---------------------------------------------------
__device__ __half g_vh[(size_t)MAXN * DIM];   // v in fp16
__device__ float  g_comb[(size_t)MAXN * DIM];
__device__ float  g_bq[MAXN];
__device__ float  g_denom[MAXN];
__device__ __half g_bh_v[DIM * DIM];          // Wk^T as fp16, [k][n]
__device__ __half g_bh_g[2 * DIM * DIM];      // Wg   as fp16, [k][n]
__device__ int    g_cnt[MAXN];
__device__ int    g_bucket[(size_t)MAXN * BCAP];
__device__ int    g_ovf[MAXE];
__device__ int    g_ovf_cnt;

// ---------------- helpers ---------------------------------------------------
__device__ __forceinline__ uint32_t smem_u32(const void* p) {
    uint32_t a;
    asm("{ .reg .u64 t; cvta.to.shared.u64 t, %1; cvt.u32.u64 %0, t; }" : "=r"(a) : "l"(p));
    return a;
}
__device__ __forceinline__ void red_add_v4(float* addr, float a, float b, float c, float d) {
    asm volatile("red.global.add.v4.f32 [%0], {%1,%2,%3,%4};"
                 :: "l"(addr), "f"(a), "f"(b), "f"(c), "f"(d) : "memory");
}
__device__ __forceinline__ void cp_async16(uint32_t saddr, const void* gaddr) {
    asm volatile("cp.async.ca.shared.global [%0], [%1], 16;\n" :: "r"(saddr), "l"(gaddr));
}
__device__ __forceinline__ void cp_commit() {
    asm volatile("cp.async.commit_group;\n");
}
__device__ __forceinline__ void ldsm_x4(uint32_t r[4], uint32_t addr) {
    asm volatile("ldmatrix.sync.aligned.m8n8.x4.shared.b16 {%0,%1,%2,%3}, [%4];"
                 : "=r"(r[0]), "=r"(r[1]), "=r"(r[2]), "=r"(r[3]) : "r"(addr));
}
__device__ __forceinline__ void ldsm_x4_t(uint32_t r[4], uint32_t addr) {
    asm volatile("ldmatrix.sync.aligned.m8n8.x4.trans.shared.b16 {%0,%1,%2,%3}, [%4];"
                 : "=r"(r[0]), "=r"(r[1]), "=r"(r[2]), "=r"(r[3]) : "r"(addr));
}
__device__ __forceinline__ void mma_f16(float c[4], const uint32_t a[4], uint32_t b0, uint32_t b1) {
    asm volatile(
        "mma.sync.aligned.m16n8k16.row.col.f32.f16.f16.f32 "
        "{%0,%1,%2,%3}, {%4,%5,%6,%7}, {%8,%9}, {%0,%1,%2,%3};"
        : "+f"(c[0]), "+f"(c[1]), "+f"(c[2]), "+f"(c[3])
        : "r"(a[0]), "r"(a[1]), "r"(a[2]), "r"(a[3]), "r"(b0), "r"(b1));
}

// ---------------- prep: fp16 B images ----------------------------------------
__global__ void k_h_wkT(const float* __restrict__ Wk, __half* __restrict__ dst) {
    __shared__ float t[32][33];
    int bk = blockIdx.x * 32, bn = blockIdx.y * 32;
    int tx = threadIdx.x, ty = threadIdx.y;
    #pragma unroll
    for (int i = 0; i < 32; i += 8)
        t[ty + i][tx] = Wk[(bn + ty + i) * DIM + bk + tx];
    __syncthreads();
    #pragma unroll
    for (int i = 0; i < 32; i += 8)
        dst[(size_t)(bk + ty + i) * DIM + bn + tx] = __float2half(t[tx][ty + i]);
}
__global__ void k_h_wg(const float* __restrict__ Wg, __half* __restrict__ dst) {
    int i = blockIdx.x * blockDim.x + threadIdx.x;
    if (i < 2 * DIM * DIM) dst[i] = __float2half(Wg[i]);
}

// ---------------- bucketing --------------------------------------------------
__global__ void k_zero_cnt(int N) {
    int i = blockIdx.x * blockDim.x + threadIdx.x;
    if (i < N) g_cnt[i] = 0;
    if (i == 0) g_ovf_cnt = 0;
}
__global__ void k_bucket(const int* __restrict__ idx, int E) {
    int e = blockIdx.x * blockDim.x + threadIdx.x;
    if (e >= E) return;
    int n = __ldg(idx + e);
    int r = atomicAdd(&g_cnt[n], 1);
    if (r < BCAP) g_bucket[(size_t)n * BCAP + r] = e;
    else          g_ovf[atomicAdd(&g_ovf_cnt, 1)] = e;
}

// ---------------- edge phase: one warp per node, register accumulation -------
__global__ __launch_bounds__(256) void k_edge_n(const float* __restrict__ x, int N) {
    int warp = threadIdx.x >> 5, lane = threadIdx.x & 31;
    int n = blockIdx.x * 8 + warp;
    if (n >= N) return;

    int c = g_cnt[n]; if (c > BCAP) c = BCAP;
    float4* cb = (float4*)(g_comb + (size_t)n * DIM);

    if (c == 0) {
        float4 z = make_float4(0.f, 0.f, 0.f, 0.f);
        cb[lane] = z; cb[lane + 32] = z;
        if (lane == 0) g_denom[n] = 0.f;
        return;
    }

    // v row (fp16, dense): lane covers cols 4*lane.. and 128+4*lane..
    const uint2* vp = (const uint2*)(g_vh + (size_t)n * DIM);
    uint2 h0 = vp[lane], h1 = vp[lane + 32];
    float2 v0 = __half22float2(*(__half2*)&h0.x);
    float2 v1 = __half22float2(*(__half2*)&h0.y);
    float2 v2 = __half22float2(*(__half2*)&h1.x);
    float2 v3 = __half22float2(*(__half2*)&h1.y);
    float bqn = g_bq[n];

    const int* bkt = g_bucket + (size_t)n * BCAP;
    int e = __ldg(bkt);
    const float4* xp = (const float4*)(x + (size_t)e * DIM);
    float4 a0 = __ldcs(xp + lane);
    float4 a1 = __ldcs(xp + lane + 32);

    float den = 0.f;
    float4 acc0 = make_float4(0.f, 0.f, 0.f, 0.f);
    float4 acc1 = make_float4(0.f, 0.f, 0.f, 0.f);

    for (int j = 0; j < c; j++) {
        float4 b0, b1;                 // prefetch next edge's x under the reduce chain
        if (j + 1 < c) {
            int e2 = __ldg(bkt + j + 1);
            const float4* xp2 = (const float4*)(x + (size_t)e2 * DIM);
            b0 = __ldcs(xp2 + lane);
            b1 = __ldcs(xp2 + lane + 32);
        }
        float s = a0.x * v0.x + a0.y * v0.y + a0.z * v1.x + a0.w * v1.y
                + a1.x * v2.x + a1.y * v2.y + a1.z * v3.x + a1.w * v3.y;
        #pragma unroll
        for (int o = 16; o; o >>= 1) s += __shfl_xor_sync(0xffffffffu, s, o);
        float ex = expf((s + bqn) * 0.0625f);
        den += ex;
        acc0.x += ex * a0.x; acc0.y += ex * a0.y; acc0.z += ex * a0.z; acc0.w += ex * a0.w;
        acc1.x += ex * a1.x; acc1.y += ex * a1.y; acc1.z += ex * a1.z; acc1.w += ex * a1.w;
        a0 = b0; a1 = b1;
    }

    cb[lane] = acc0;
    cb[lane + 32] = acc1;
    if (lane == 0) g_denom[n] = den;
}

// cleanup for bucket overflow (normally 0 edges): old atomic path
__global__ __launch_bounds__(256) void k_edge_ovf(const float* __restrict__ x,
                                                  const int* __restrict__ idx) {
    int total = g_ovf_cnt;
    if (total <= 0) return;
    int warp = threadIdx.x >> 5, lane = threadIdx.x & 31;
    for (int i = blockIdx.x * 8 + warp; i < total; i += gridDim.x * 8) {
        int e = g_ovf[i];
        int n = __ldg(idx + e);
        const float4* xp = (const float4*)(x + (size_t)e * DIM);
        const uint2*  vp = (const uint2*)(g_vh + (size_t)n * DIM);
        float4 a0 = xp[lane], a1 = xp[lane + 32];
        uint2 h0 = vp[lane], h1 = vp[lane + 32];
        float2 v0 = __half22float2(*(__half2*)&h0.x);
        float2 v1 = __half22float2(*(__half2*)&h0.y);
        float2 v2 = __half22float2(*(__half2*)&h1.x);
        float2 v3 = __half22float2(*(__half2*)&h1.y);
        float s = a0.x * v0.x + a0.y * v0.y + a0.z * v1.x + a0.w * v1.y
                + a1.x * v2.x + a1.y * v2.y + a1.z * v3.x + a1.w * v3.y;
        #pragma unroll
        for (int o = 16; o; o >>= 1) s += __shfl_xor_sync(0xffffffffu, s, o);
        float ex = expf((s + g_bq[n]) * 0.0625f);
        if (lane == 0) atomicAdd(&g_denom[n], ex);
        float* cbf = g_comb + (size_t)n * DIM;
        red_add_v4(cbf + (size_t)lane * 4,        ex * a0.x, ex * a0.y, ex * a0.z, ex * a0.w);
        red_add_v4(cbf + (size_t)(lane + 32) * 4, ex * a1.x, ex * a1.y, ex * a1.z, ex * a1.w);
    }
}

// ---------------- fp16 tensor-core GEMM, BM=64 x BN=256, BK=32 ---------------
#define BM 64
#define BN 256
#define BK 32
#define ASTRH 40
#define BSTRH 264

template<int KT, bool GATE>
__global__ __launch_bounds__(256, 2) void k_gemm_h(const float* __restrict__ Aprev,
                                                   const float* __restrict__ bias,
                                                   float* __restrict__ out, int M) {
    __shared__ __half As[2][BM * ASTRH];
    __shared__ __half Bs[2][BK * BSTRH];
    __shared__ float  bks[DIM];
    __shared__ float  invs[BM];

    const int tid  = threadIdx.x;
    const int lane = tid & 31;
    const int g    = lane >> 2;
    const int tg   = lane & 3;
    const int wid  = tid >> 5;
    const int wR   = (wid & 1) * 32;
    const int wCat = (wid >> 1) * 8;
    const int bm   = blockIdx.x * BM;
    const int lj   = lane >> 3;
    const int lr   = lane & 7;

    if (tid < 64) *(float4*)&bks[tid * 4] = *(const float4*)(bias + tid * 4);
    if (GATE && tid < BM) {
        int r = bm + tid;
        float d = (r < M) ? g_denom[r] : 1.f;
        invs[tid] = 1.f / fmaxf(d, 1e-9f);
    }
    __syncthreads();

    float c[2][8][4];
    #pragma unroll
    for (int mi = 0; mi < 2; mi++)
        #pragma unroll
        for (int ni = 0; ni < 8; ni++)
            #pragma unroll
            for (int q = 0; q < 4; q++) c[mi][ni][q] = 0.f;

    auto ldgA = [&](int it, float4 v[2]) {
        const float* asrc; int k0;
        if (GATE) { if (it < 8) { asrc = (const float*)g_comb; k0 = it * 32; }
                    else        { asrc = Aprev;                k0 = (it - 8) * 32; } }
        else      { asrc = Aprev; k0 = it * 32; }
        #pragma unroll
        for (int j = 0; j < 2; j++) {
            int seg = tid + j * 256;
            int row = seg >> 3, c4 = (seg & 7) * 4;
            int gr = bm + row; if (gr >= M) gr = M - 1;
            v[j] = *(const float4*)(asrc + (size_t)gr * DIM + k0 + c4);
        }
    };
    auto stsA = [&](int it, int buf, const float4 v[2]) {
        bool sc = GATE && (it < 8);
        #pragma unroll
        for (int j = 0; j < 2; j++) {
            int seg = tid + j * 256;
            int row = seg >> 3, c4 = (seg & 7) * 4;
            float4 w = v[j];
            if (sc) { float iv = invs[row]; w.x *= iv; w.y *= iv; w.z *= iv; w.w *= iv; }
            __half2 h0 = __floats2half2_rn(w.x, w.y);
            __half2 h1 = __floats2half2_rn(w.z, w.w);
            uint2 pk = make_uint2(*(uint32_t*)&h0, *(uint32_t*)&h1);
            *(uint2*)&As[buf][row * ASTRH + c4] = pk;
        }
    };
    auto stageB = [&](int it, int buf) {
        const __half* bh = GATE ? (const __half*)g_bh_g : (const __half*)g_bh_v;
        int kb = GATE ? (it < 8 ? 256 + it * 32 : (it - 8) * 32) : it * 32;
        #pragma unroll
        for (int j = 0; j < 4; j++) {
            int seg = tid + j * 256;
            int kr = seg >> 5, c8 = (seg & 31) * 8;
            cp_async16(smem_u32(&Bs[buf][kr * BSTRH + c8]),
                       bh + (size_t)(kb + kr) * DIM + c8);
        }
        cp_commit();
    };

    float4 vA[2], vN[2];
    ldgA(0, vA); stsA(0, 0, vA); stageB(0, 0);

    float bqacc = 0.f;
    const int bq_row = tid >> 2;
    const int bq_q   = tid & 3;

    #pragma unroll 1
    for (int it = 0; it < KT; it++) {
        int buf = it & 1;
        if (it + 1 < KT) {
            ldgA(it + 1, vN);
            stageB(it + 1, (it + 1) & 1);
            asm volatile("cp.async.wait_group 1;\n" ::: "memory");
        } else {
            asm volatile("cp.async.wait_group 0;\n" ::: "memory");
        }
        __syncthreads();

        const __half* Ab = As[buf];
        const __half* Bb = Bs[buf];
        #pragma unroll
        for (int ks = 0; ks < BK; ks += 16) {
            uint32_t a[2][4];
            #pragma unroll
            for (int mi = 0; mi < 2; mi++) {
                uint32_t ad = smem_u32(&Ab[(wR + mi * 16 + (lj & 1) * 8 + lr) * ASTRH
                                           + ks + (lj >> 1) * 8]);
                ldsm_x4(a[mi], ad);
            }
            #pragma unroll
            for (int nn = 0; nn < 4; nn++) {
                uint32_t b[4];
                uint32_t bd = smem_u32(&Bb[(ks + (lj & 1) * 8 + lr) * BSTRH
                                           + (wCat + nn * 2 + (lj >> 1)) * 8]);
                ldsm_x4_t(b, bd);
                #pragma unroll
                for (int mi = 0; mi < 2; mi++) {
                    mma_f16(c[mi][nn * 2 + 0], a[mi], b[0], b[1]);
                    mma_f16(c[mi][nn * 2 + 1], a[mi], b[2], b[3]);
                }
            }
        }

        if (!GATE) {
            float s = 0.f;
            #pragma unroll
            for (int j = 0; j < 8; j++)
                s += __half2float(Ab[bq_row * ASTRH + bq_q * 8 + j])
                   * bks[it * 32 + bq_q * 8 + j];
            bqacc += s;
        }

        if (it + 1 < KT) stsA(it + 1, (it + 1) & 1, vN);
        __syncthreads();
    }

    if (!GATE) {
        bqacc += __shfl_xor_sync(0xffffffffu, bqacc, 1);
        bqacc += __shfl_xor_sync(0xffffffffu, bqacc, 2);
        if (bq_q == 0 && bm + bq_row < M) g_bq[bm + bq_row] = bqacc;
    }

    #pragma unroll
    for (int mi = 0; mi < 2; mi++) {
        #pragma unroll
        for (int half = 0; half < 2; half++) {
            int lrow = wR + mi * 16 + g + half * 8;
            int r = bm + lrow;
            if (r >= M) continue;
            #pragma unroll
            for (int ni = 0; ni < 8; ni++) {
                int cc = wCat * 8 + ni * 8 + tg * 2;
                float v0 = c[mi][ni][half * 2 + 0];
                float v1 = c[mi][ni][half * 2 + 1];
                if (GATE) {
                    float2 pv = *(const float2*)(Aprev + (size_t)r * DIM + cc);
                    float2 cv = *(const float2*)(g_comb + (size_t)r * DIM + cc);
                    float iv = invs[lrow];
                    float g0 = 1.f / (1.f + expf(-(v0 + bks[cc])));
                    float g1 = 1.f / (1.f + expf(-(v1 + bks[cc + 1])));
                    float2 o;
                    o.x = g0 * pv.x + (1.f - g0) * (cv.x * iv);
                    o.y = g1 * pv.y + (1.f - g1) * (cv.y * iv);
                    *(float2*)(out + (size_t)r * DIM + cc) = o;
                } else {
                    __half2 hv = __floats2half2_rn(v0, v1);
                    *(uint32_t*)(g_vh + (size_t)r * DIM + cc) = *(uint32_t*)&hv;
                }
            }
        }
    }
}

// ---------------- launch ------------------------------------------------------
extern "C" void kernel_launch(void* const* d_in, const int* in_sizes, int n_in,
                              void* d_out, int out_size) {
    const float* x    = (const float*)d_in[0];
    const float* prev = (const float*)d_in[1];
    const float* Wk   = (const float*)d_in[2];
    const float* bk   = (const float*)d_in[3];
    const float* Wg   = (const float*)d_in[4];
    const float* bg   = (const float*)d_in[5];
    const int*   idx  = (const int*)d_in[6];
    float* out = (float*)d_out;

    int Dv = in_sizes[3];            // 256
    int E  = in_sizes[0] / Dv;
    int N  = in_sizes[1] / Dv;

    __half* bhv = nullptr; cudaGetSymbolAddress((void**)&bhv, g_bh_v);
    __half* bhg = nullptr; cudaGetSymbolAddress((void**)&bhg, g_bh_g);
    k_h_wkT<<<dim3(8, 8), dim3(32, 8)>>>(Wk, bhv);
    k_h_wg<<<(2 * DIM * DIM + 255) / 256, 256>>>(Wg, bhg);
    k_zero_cnt<<<(N + 255) / 256, 256>>>(N);
    k_bucket<<<(E + 255) / 256, 256>>>(idx, E);

    int gb = (N + BM - 1) / BM;
    k_gemm_h<8, false><<<gb, 256>>>(prev, bk, nullptr, N);

    k_edge_n<<<(N + 7) / 8, 256>>>(x, N);
    k_edge_ovf<<<64, 256>>>(x, idx);

    k_gemm_h<16, true><<<gb, 256>>>(prev, bg, out, N);
}

// round 14
// speedup vs baseline: 1.2276x; 1.0304x over previous
#include <cuda_runtime.h>
#include <cuda_fp16.h>
#include <math.h>
#include <stdint.h>

#define DIM   256
#define MAXN  100000
#define MAXE  500000
#define BCAP  64

// ---------------- scratch ---------------------------------------------------
__device__ __half g_vh[(size_t)MAXN * DIM];     // v in fp16
__device__ __half g_combh[(size_t)MAXN * DIM];  // NORMALIZED comb in fp16
__device__ float  g_bq[MAXN];
__device__ __half g_bh_v[DIM * DIM];            // Wk^T as fp16, [k][n]
__device__ __half g_bh_g[2 * DIM * DIM];        // Wg   as fp16, [k][n]
__device__ int    g_cnt[MAXN];
__device__ int    g_bucket[(size_t)MAXN * BCAP];
__device__ int    g_ovf[MAXE];
__device__ int    g_ovf_cnt;

// ---------------- helpers ---------------------------------------------------
__device__ __forceinline__ uint32_t smem_u32(const void* p) {
    uint32_t a;
    asm("{ .reg .u64 t; cvta.to.shared.u64 t, %1; cvt.u32.u64 %0, t; }" : "=r"(a) : "l"(p));
    return a;
}
__device__ __forceinline__ void cp_async16(uint32_t saddr, const void* gaddr) {
    asm volatile("cp.async.ca.shared.global [%0], [%1], 16;\n" :: "r"(saddr), "l"(gaddr));
}
__device__ __forceinline__ void cp_commit() {
    asm volatile("cp.async.commit_group;\n");
}
__device__ __forceinline__ void ldsm_x4(uint32_t r[4], uint32_t addr) {
    asm volatile("ldmatrix.sync.aligned.m8n8.x4.shared.b16 {%0,%1,%2,%3}, [%4];"
                 : "=r"(r[0]), "=r"(r[1]), "=r"(r[2]), "=r"(r[3]) : "r"(addr));
}
__device__ __forceinline__ void ldsm_x4_t(uint32_t r[4], uint32_t addr) {
    asm volatile("ldmatrix.sync.aligned.m8n8.x4.trans.shared.b16 {%0,%1,%2,%3}, [%4];"
                 : "=r"(r[0]), "=r"(r[1]), "=r"(r[2]), "=r"(r[3]) : "r"(addr));
}
__device__ __forceinline__ void mma_f16(float c[4], const uint32_t a[4], uint32_t b0, uint32_t b1) {
    asm volatile(
        "mma.sync.aligned.m16n8k16.row.col.f32.f16.f16.f32 "
        "{%0,%1,%2,%3}, {%4,%5,%6,%7}, {%8,%9}, {%0,%1,%2,%3};"
        : "+f"(c[0]), "+f"(c[1]), "+f"(c[2]), "+f"(c[3])
        : "r"(a[0]), "r"(a[1]), "r"(a[2]), "r"(a[3]), "r"(b0), "r"(b1));
}

// ---------------- prep: fp16 B images + cnt zeroing --------------------------
__global__ void k_h_wkT(const float* __restrict__ Wk, __half* __restrict__ dst) {
    __shared__ float t[32][33];
    int bk = blockIdx.x * 32, bn = blockIdx.y * 32;
    int tx = threadIdx.x, ty = threadIdx.y;
    #pragma unroll
    for (int i = 0; i < 32; i += 8)
        t[ty + i][tx] = Wk[(bn + ty + i) * DIM + bk + tx];
    __syncthreads();
    #pragma unroll
    for (int i = 0; i < 32; i += 8)
        dst[(size_t)(bk + ty + i) * DIM + bn + tx] = __float2half(t[tx][ty + i]);
}
__global__ void k_h_wg(const float* __restrict__ Wg, __half* __restrict__ dst, int N) {
    int i = blockIdx.x * blockDim.x + threadIdx.x;
    if (i < 2 * DIM * DIM) dst[i] = __float2half(Wg[i]);
    if (i < N) g_cnt[i] = 0;            // fused counter zeroing
    if (i == 0) g_ovf_cnt = 0;
}

// ---------------- bucketing --------------------------------------------------
__global__ void k_bucket(const int* __restrict__ idx, int E) {
    int e = blockIdx.x * blockDim.x + threadIdx.x;
    if (e >= E) return;
    int n = __ldg(idx + e);
    int r = atomicAdd(&g_cnt[n], 1);
    if (r < BCAP) g_bucket[(size_t)n * BCAP + r] = e;
    else          g_ovf[atomicAdd(&g_ovf_cnt, 1)] = e;
}

// ---------------- edge phase: warp/node, normalize-early, fp16 store ---------
__global__ __launch_bounds__(256) void k_edge_n(const float* __restrict__ x,
                                                const int* __restrict__ idx, int N) {
    int warp = threadIdx.x >> 5, lane = threadIdx.x & 31;
    int n = blockIdx.x * 8 + warp;
    if (n >= N) return;

    int c_full = g_cnt[n];
    int c = c_full < BCAP ? c_full : BCAP;
    uint2* cbh0 = (uint2*)(g_combh + (size_t)n * DIM + (size_t)lane * 4);
    uint2* cbh1 = (uint2*)(g_combh + (size_t)n * DIM + 128 + (size_t)lane * 4);

    if (c_full == 0) {
        uint2 z = make_uint2(0u, 0u);
        *cbh0 = z; *cbh1 = z;
        return;
    }

    const uint2* vp = (const uint2*)(g_vh + (size_t)n * DIM);
    uint2 h0 = vp[lane], h1 = vp[lane + 32];
    float2 v0 = __half22float2(*(__half2*)&h0.x);
    float2 v1 = __half22float2(*(__half2*)&h0.y);
    float2 v2 = __half22float2(*(__half2*)&h1.x);
    float2 v3 = __half22float2(*(__half2*)&h1.y);
    float bqn = g_bq[n];

    const int* bkt = g_bucket + (size_t)n * BCAP;
    int e = __ldg(bkt);
    const float4* xp = (const float4*)(x + (size_t)e * DIM);
    float4 a0 = __ldcs(xp + lane);
    float4 a1 = __ldcs(xp + lane + 32);

    float den = 0.f;
    float4 acc0 = make_float4(0.f, 0.f, 0.f, 0.f);
    float4 acc1 = make_float4(0.f, 0.f, 0.f, 0.f);

    for (int j = 0; j < c; j++) {
        float4 b0, b1;
        if (j + 1 < c) {
            int e2 = __ldg(bkt + j + 1);
            const float4* xp2 = (const float4*)(x + (size_t)e2 * DIM);
            b0 = __ldcs(xp2 + lane);
            b1 = __ldcs(xp2 + lane + 32);
        }
        float s = a0.x * v0.x + a0.y * v0.y + a0.z * v1.x + a0.w * v1.y
                + a1.x * v2.x + a1.y * v2.y + a1.z * v3.x + a1.w * v3.y;
        #pragma unroll
        for (int o = 16; o; o >>= 1) s += __shfl_xor_sync(0xffffffffu, s, o);
        float ex = expf((s + bqn) * 0.0625f);
        den += ex;
        acc0.x += ex * a0.x; acc0.y += ex * a0.y; acc0.z += ex * a0.z; acc0.w += ex * a0.w;
        acc1.x += ex * a1.x; acc1.y += ex * a1.y; acc1.z += ex * a1.z; acc1.w += ex * a1.w;
        a0 = b0; a1 = b1;
    }

    if (c_full > BCAP) {                      // rare overflow: scan tiny ovf list
        int t = g_ovf_cnt;
        for (int i = 0; i < t; i++) {
            int e2 = g_ovf[i];
            if (__ldg(idx + e2) != n) continue;
            const float4* xp2 = (const float4*)(x + (size_t)e2 * DIM);
            float4 c0 = xp2[lane], c1 = xp2[lane + 32];
            float s = c0.x * v0.x + c0.y * v0.y + c0.z * v1.x + c0.w * v1.y
                    + c1.x * v2.x + c1.y * v2.y + c1.z * v3.x + c1.w * v3.y;
            #pragma unroll
            for (int o = 16; o; o >>= 1) s += __shfl_xor_sync(0xffffffffu, s, o);
            float ex = expf((s + bqn) * 0.0625f);
            den += ex;
            acc0.x += ex * c0.x; acc0.y += ex * c0.y; acc0.z += ex * c0.z; acc0.w += ex * c0.w;
            acc1.x += ex * c1.x; acc1.y += ex * c1.y; acc1.z += ex * c1.z; acc1.w += ex * c1.w;
        }
    }

    float inv = 1.f / fmaxf(den, 1e-9f);      // normalize early
    __half2 p0 = __floats2half2_rn(acc0.x * inv, acc0.y * inv);
    __half2 p1 = __floats2half2_rn(acc0.z * inv, acc0.w * inv);
    __half2 p2 = __floats2half2_rn(acc1.x * inv, acc1.y * inv);
    __half2 p3 = __floats2half2_rn(acc1.z * inv, acc1.w * inv);
    *cbh0 = make_uint2(*(uint32_t*)&p0, *(uint32_t*)&p1);
    *cbh1 = make_uint2(*(uint32_t*)&p2, *(uint32_t*)&p3);
}

// ---------------- fp16 tensor-core GEMM, BM=64 x BN=256, BK=32 ---------------
#define BM 64
#define BN 256
#define BK 32
#define ASTRH 40
#define BSTRH 264

template<int KT, bool GATE>
__global__ __launch_bounds__(256, 2) void k_gemm_h(const float* __restrict__ Aprev,
                                                   const float* __restrict__ bias,
                                                   float* __restrict__ out, int M) {
    __shared__ __half As[2][BM * ASTRH];
    __shared__ __half Bs[2][BK * BSTRH];
    __shared__ float  bks[DIM];

    const int tid  = threadIdx.x;
    const int lane = tid & 31;
    const int g    = lane >> 2;
    const int tg   = lane & 3;
    const int wid  = tid >> 5;
    const int wR   = (wid & 1) * 32;
    const int wCat = (wid >> 1) * 8;
    const int bm   = blockIdx.x * BM;
    const int lj   = lane >> 3;
    const int lr   = lane & 7;

    if (tid < 64) *(float4*)&bks[tid * 4] = *(const float4*)(bias + tid * 4);
    __syncthreads();

    float c[2][8][4];
    #pragma unroll
    for (int mi = 0; mi < 2; mi++)
        #pragma unroll
        for (int ni = 0; ni < 8; ni++)
            #pragma unroll
            for (int q = 0; q < 4; q++) c[mi][ni][q] = 0.f;

    // GATE it<8: A = g_combh (fp16, normalized) staged via cp.async.
    // otherwise: A = prev (fp32) via LDG-convert-STS.
    auto a_is_cp = [&](int it) { return GATE && it < 8; };

    auto stageA_cp = [&](int it, int buf) {       // 64 rows x 32 halves = 256x16B
        int k0 = it * 32;
        int row = tid >> 2, c8 = (tid & 3) * 8;
        int gr = bm + row; if (gr >= M) gr = M - 1;
        cp_async16(smem_u32(&As[buf][row * ASTRH + c8]),
                   g_combh + (size_t)gr * DIM + k0 + c8);
    };
    auto ldgA = [&](int it, float4 v[2]) {
        int k0 = GATE ? (it - 8) * 32 : it * 32;
        #pragma unroll
        for (int j = 0; j < 2; j++) {
            int seg = tid + j * 256;
            int row = seg >> 3, c4 = (seg & 7) * 4;
            int gr = bm + row; if (gr >= M) gr = M - 1;
            v[j] = *(const float4*)(Aprev + (size_t)gr * DIM + k0 + c4);
        }
    };
    auto stsA = [&](int buf, const float4 v[2]) {
        #pragma unroll
        for (int j = 0; j < 2; j++) {
            int seg = tid + j * 256;
            int row = seg >> 3, c4 = (seg & 7) * 4;
            __half2 h0 = __floats2half2_rn(v[j].x, v[j].y);
            __half2 h1 = __floats2half2_rn(v[j].z, v[j].w);
            uint2 pk = make_uint2(*(uint32_t*)&h0, *(uint32_t*)&h1);
            *(uint2*)&As[buf][row * ASTRH + c4] = pk;
        }
    };
    auto stageB = [&](int it, int buf) {
        const __half* bh = GATE ? (const __half*)g_bh_g : (const __half*)g_bh_v;
        int kb = GATE ? (it < 8 ? 256 + it * 32 : (it - 8) * 32) : it * 32;
        #pragma unroll
        for (int j = 0; j < 4; j++) {
            int seg = tid + j * 256;
            int kr = seg >> 5, c8 = (seg & 31) * 8;
            cp_async16(smem_u32(&Bs[buf][kr * BSTRH + c8]),
                       bh + (size_t)(kb + kr) * DIM + c8);
        }
    };

    float4 vA[2], vN[2];
    bool pendN = false;
    if (a_is_cp(0)) stageA_cp(0, 0);
    else { ldgA(0, vA); stsA(0, vA); }
    stageB(0, 0);
    cp_commit();

    float bqacc = 0.f;
    const int bq_row = tid >> 2;
    const int bq_q   = tid & 3;

    #pragma unroll 1
    for (int it = 0; it < KT; it++) {
        int buf = it & 1;
        if (it + 1 < KT) {
            int nb = (it + 1) & 1;
            if (a_is_cp(it + 1)) { stageA_cp(it + 1, nb); pendN = false; }
            else                 { ldgA(it + 1, vN);      pendN = true;  }
            stageB(it + 1, nb);
            cp_commit();
            asm volatile("cp.async.wait_group 1;\n" ::: "memory");
        } else {
            asm volatile("cp.async.wait_group 0;\n" ::: "memory");
        }
        __syncthreads();

        const __half* Ab = As[buf];
        const __half* Bb = Bs[buf];
        #pragma unroll
        for (int ks = 0; ks < BK; ks += 16) {
            uint32_t a[2][4];
            #pragma unroll
            for (int mi = 0; mi < 2; mi++) {
                uint32_t ad = smem_u32(&Ab[(wR + mi * 16 + (lj & 1) * 8 + lr) * ASTRH
                                           + ks + (lj >> 1) * 8]);
                ldsm_x4(a[mi], ad);
            }
            #pragma unroll
            for (int nn = 0; nn < 4; nn++) {
                uint32_t b[4];
                uint32_t bd = smem_u32(&Bb[(ks + (lj & 1) * 8 + lr) * BSTRH
                                           + (wCat + nn * 2 + (lj >> 1)) * 8]);
                ldsm_x4_t(b, bd);
                #pragma unroll
                for (int mi = 0; mi < 2; mi++) {
                    mma_f16(c[mi][nn * 2 + 0], a[mi], b[0], b[1]);
                    mma_f16(c[mi][nn * 2 + 1], a[mi], b[2], b[3]);
                }
            }
        }

        if (!GATE) {
            float s = 0.f;
            #pragma unroll
            for (int j = 0; j < 8; j++)
                s += __half2float(Ab[bq_row * ASTRH + bq_q * 8 + j])
                   * bks[it * 32 + bq_q * 8 + j];
            bqacc += s;
        }

        if (it + 1 < KT && pendN) stsA((it + 1) & 1, vN);
        __syncthreads();
    }

    if (!GATE) {
        bqacc += __shfl_xor_sync(0xffffffffu, bqacc, 1);
        bqacc += __shfl_xor_sync(0xffffffffu, bqacc, 2);
        if (bq_q == 0 && bm + bq_row < M) g_bq[bm + bq_row] = bqacc;
    }

    #pragma unroll
    for (int mi = 0; mi < 2; mi++) {
        #pragma unroll
        for (int half = 0; half < 2; half++) {
            int r = bm + wR + mi * 16 + g + half * 8;
            if (r >= M) continue;
            #pragma unroll
            for (int ni = 0; ni < 8; ni++) {
                int cc = wCat * 8 + ni * 8 + tg * 2;
                float v0 = c[mi][ni][half * 2 + 0];
                float v1 = c[mi][ni][half * 2 + 1];
                if (GATE) {
                    float2 pv = *(const float2*)(Aprev + (size_t)r * DIM + cc);
                    uint32_t ch = *(const uint32_t*)(g_combh + (size_t)r * DIM + cc);
                    float2 cv = __half22float2(*(__half2*)&ch);
                    float g0 = 1.f / (1.f + expf(-(v0 + bks[cc])));
                    float g1 = 1.f / (1.f + expf(-(v1 + bks[cc + 1])));
                    float2 o;
                    o.x = g0 * pv.x + (1.f - g0) * cv.x;
                    o.y = g1 * pv.y + (1.f - g1) * cv.y;
                    *(float2*)(out + (size_t)r * DIM + cc) = o;
                } else {
                    __half2 hv = __floats2half2_rn(v0, v1);
                    *(uint32_t*)(g_vh + (size_t)r * DIM + cc) = *(uint32_t*)&hv;
                }
            }
        }
    }
}

// ---------------- launch ------------------------------------------------------
extern "C" void kernel_launch(void* const* d_in, const int* in_sizes, int n_in,
                              void* d_out, int out_size) {
    const float* x    = (const float*)d_in[0];
    const float* prev = (const float*)d_in[1];
    const float* Wk   = (const float*)d_in[2];
    const float* bk   = (const float*)d_in[3];
    const float* Wg   = (const float*)d_in[4];
    const float* bg   = (const float*)d_in[5];
    const int*   idx  = (const int*)d_in[6];
    float* out = (float*)d_out;

    int Dv = in_sizes[3];            // 256
    int E  = in_sizes[0] / Dv;
    int N  = in_sizes[1] / Dv;

    __half* bhv = nullptr; cudaGetSymbolAddress((void**)&bhv, g_bh_v);
    __half* bhg = nullptr; cudaGetSymbolAddress((void**)&bhg, g_bh_g);
    k_h_wkT<<<dim3(8, 8), dim3(32, 8)>>>(Wk, bhv);
    k_h_wg<<<(2 * DIM * DIM + 255) / 256, 256>>>(Wg, bhg, N);
    k_bucket<<<(E + 255) / 256, 256>>>(idx, E);

    int gb = (N + BM - 1) / BM;
    k_gemm_h<8, false><<<gb, 256>>>(prev, bk, nullptr, N);

    k_edge_n<<<(N + 7) / 8, 256>>>(x, idx, N);

    k_gemm_h<16, true><<<gb, 256>>>(prev, bg, out, N);
}